// round 7
// baseline (speedup 1.0000x reference)
#include <cuda_runtime.h>
#include <cuda_fp16.h>
#include <cstdint>

#define N_OBS 2048
#define KH    1024
#define DIN   64
#define NTILE 8          // KH / 128
#define NPAIR 36         // upper-triangle tile pairs
#define NSPLIT 8         // split-K factor for kernelB
#define NGRP  4          // pipeline groups (9 pairs each)

// Scratch (device globals: allocation-free per harness rules)
__device__ __half g_sT[KH * N_OBS];                  // 4 MB: sin activations fp16, (k, n)
__device__ float  g_M[KH * KH];                      // 4 MB: full symmetric Gram
__device__ float  g_Mp[NSPLIT * NPAIR * 128 * 128];  // 18.9 MB: per-(split,tile) partials

// ---------------------------------------------------------------------------
// Helpers (compute_103-portable)
// ---------------------------------------------------------------------------
__device__ __forceinline__ void pair_from_idx(int idx, int& tr, int& tc) {
    int t = 0, rem = idx;
    while (rem >= NTILE - t) { rem -= NTILE - t; t++; }
    tr = t; tc = t + rem;
}
__device__ __forceinline__ int idx_from_pair(int tr, int tc) {
    return tr * NTILE - (tr * (tr - 1)) / 2 + (tc - tr);
}
__device__ __forceinline__ uint32_t smem_u32(const void* p) {
    uint32_t a;
    asm("{ .reg .u64 t; cvta.to.shared.u64 t, %1; cvt.u32.u64 %0, t; }" : "=r"(a) : "l"(p));
    return a;
}
__device__ __forceinline__ void cp_async16(uint32_t dst, const void* src) {
    asm volatile("cp.async.cg.shared.global [%0], [%1], 16;" :: "r"(dst), "l"(src));
}
#define CP_COMMIT() asm volatile("cp.async.commit_group;" ::: "memory")
#define CP_WAIT1()  asm volatile("cp.async.wait_group 1;" ::: "memory")
#define CP_WAIT0()  asm volatile("cp.async.wait_group 0;" ::: "memory")

__device__ __forceinline__ void ldmatrix_x4(uint32_t* r, uint32_t addr) {
    asm volatile("ldmatrix.sync.aligned.m8n8.x4.shared.b16 {%0,%1,%2,%3}, [%4];"
                 : "=r"(r[0]), "=r"(r[1]), "=r"(r[2]), "=r"(r[3]) : "r"(addr));
}
__device__ __forceinline__ void mma_f16(float* c, const uint32_t* a, const uint32_t* b) {
    asm volatile(
        "mma.sync.aligned.m16n8k16.row.col.f32.f16.f16.f32 "
        "{%0,%1,%2,%3}, {%4,%5,%6,%7}, {%8,%9}, {%0,%1,%2,%3};"
        : "+f"(c[0]), "+f"(c[1]), "+f"(c[2]), "+f"(c[3])
        : "r"(a[0]), "r"(a[1]), "r"(a[2]), "r"(a[3]), "r"(b[0]), "r"(b[1]));
}

// ---------------------------------------------------------------------------
// Kernel A: g_sT[k][n] = half( __sinf( dot(x[n,:], w[k,:]) + b[k] ) )
// grid = (KH/32, N_OBS/128), 256 threads. (round-5 proven config)
// ---------------------------------------------------------------------------
#define A_KT 32
#define A_NC 128
#define A_XPAD 132

__global__ void __launch_bounds__(256) kernelA(const float* __restrict__ x,
                                               const float* __restrict__ w,
                                               const float* __restrict__ b) {
    __shared__ float xsT[DIN][A_XPAD];      // 33.8 KB  xsT[d][n_local]
    __shared__ float wks[A_KT][DIN];        // 8 KB

    const int tid = threadIdx.x;
    const int k0  = blockIdx.x * A_KT;
    const int n0  = blockIdx.y * A_NC;

    for (int i = tid; i < A_NC * DIN; i += 256) {
        const int n = i >> 6, d = i & 63;
        xsT[d][n] = x[(size_t)(n0 + n) * DIN + d];
    }
    for (int i = tid; i < A_KT * DIN; i += 256) {
        const int k = i >> 6, d = i & 63;
        wks[k][d] = w[(size_t)(k0 + k) * DIN + d];
    }
    __syncthreads();

    const int warp  = tid >> 5;
    const int lane4 = (tid & 31) * 4;
    const int r0 = warp * 4;

    float acc[4][4];
    #pragma unroll
    for (int r = 0; r < 4; r++)
        #pragma unroll
        for (int c = 0; c < 4; c++) acc[r][c] = 0.f;

    #pragma unroll 8
    for (int d = 0; d < DIN; d++) {
        const float4 xv = *(const float4*)&xsT[d][lane4];
        #pragma unroll
        for (int r = 0; r < 4; r++) {
            const float wv = wks[r0 + r][d];
            acc[r][0] += wv * xv.x; acc[r][1] += wv * xv.y;
            acc[r][2] += wv * xv.z; acc[r][3] += wv * xv.w;
        }
    }

    #pragma unroll
    for (int r = 0; r < 4; r++) {
        const float bv = b[k0 + r0 + r];
        __half2 p0 = __floats2half2_rn(__sinf(acc[r][0] + bv), __sinf(acc[r][1] + bv));
        __half2 p1 = __floats2half2_rn(__sinf(acc[r][2] + bv), __sinf(acc[r][3] + bv));
        uint2 u;
        u.x = *(uint32_t*)&p0;
        u.y = *(uint32_t*)&p1;
        *(uint2*)&g_sT[(size_t)(k0 + r0 + r) * N_OBS + n0 + lane4] = u;
    }
}

// ---------------------------------------------------------------------------
// Kernel B: partial Gram via fp16 mma + ldmatrix, cp.async double-buffered.
// grid = (9 pairs, 8 splits) per group; pairBase selects the group.
// ---------------------------------------------------------------------------
#define B_ROWB  80
#define B_OPB   (128 * B_ROWB)
#define B_BUF   (2 * B_OPB)
#define B_SMEMB (2 * B_BUF)
#define B_NCH   8                     // 256 n per CTA / 32 per chunk

__global__ void __launch_bounds__(256) kernelB_f16(int pairBase) {
    __shared__ __align__(16) char sm[B_SMEMB];

    const int tid = threadIdx.x;
    const int wid = tid >> 5;
    const int lid = tid & 31;
    const int g   = lid >> 2;
    const int t4  = lid & 3;

    const int pairIdx = pairBase + blockIdx.x;
    int tr, tc; pair_from_idx(pairIdx, tr, tc);
    const int i0 = tr * 128, l0 = tc * 128;
    const bool diag = (tr == tc);
    const int ops  = diag ? 1 : 2;
    const int nb   = blockIdx.y * (N_OBS / NSPLIT);

    const uint32_t sb = smem_u32(sm);
    const int wr = wid & 3;
    const int wc = wid >> 2;
    const int ibase = wr * 32, lbase = wc * 64;

    float c[2][8][4];
    #pragma unroll
    for (int mi = 0; mi < 2; mi++)
        #pragma unroll
        for (int ni = 0; ni < 8; ni++)
            #pragma unroll
            for (int t = 0; t < 4; t++) c[mi][ni][t] = 0.f;

    auto stage = [&](int ch, int buf) {
        const int n0 = nb + ch * 32;
        const int tot = ops << 9;
        for (int e = tid; e < tot; e += 256) {
            const int op  = e >> 9;
            const int idx = e & 511;
            const int row = idx >> 2;
            const int c16 = idx & 3;
            const int grow = (op ? l0 : i0) + row;
            cp_async16(sb + (uint32_t)(buf * B_BUF + op * B_OPB + row * B_ROWB + c16 * 16),
                       &g_sT[(size_t)grow * N_OBS + n0 + c16 * 8]);
        }
    };

    const uint32_t aOff0 = (uint32_t)((ibase + (lid & 15)) * B_ROWB + (lid >> 4) * 16);
    const uint32_t bRow  = (uint32_t)(lbase + ((lid >> 4) << 3) + (lid & 7));
    const uint32_t bOff0 = bRow * B_ROWB + ((lid >> 3) & 1) * 16;

    stage(0, 0);
    CP_COMMIT();

    for (int ch = 0; ch < B_NCH; ch++) {
        const int buf = ch & 1;
        if (ch + 1 < B_NCH) { stage(ch + 1, buf ^ 1); CP_COMMIT(); CP_WAIT1(); }
        else                { CP_WAIT0(); }
        __syncthreads();

        const uint32_t aBase = sb + buf * B_BUF;
        const uint32_t bBase = diag ? aBase : aBase + B_OPB;

        #pragma unroll
        for (int ks = 0; ks < 2; ks++) {
            uint32_t a[2][4];
            #pragma unroll
            for (int mi = 0; mi < 2; mi++)
                ldmatrix_x4(a[mi], aBase + aOff0 + (uint32_t)(mi * 16 * B_ROWB + ks * 32));
            uint32_t bb[4][4];
            #pragma unroll
            for (int p = 0; p < 4; p++)
                ldmatrix_x4(bb[p], bBase + bOff0 + (uint32_t)(p * 16 * B_ROWB + ks * 32));
            #pragma unroll
            for (int mi = 0; mi < 2; mi++)
                #pragma unroll
                for (int ni = 0; ni < 8; ni++)
                    mma_f16(c[mi][ni], a[mi], &bb[ni >> 1][(ni & 1) * 2]);
        }
        __syncthreads();
    }

    const float sc = (2.0f / (float)KH) / (float)N_OBS;
    float* dst = &g_Mp[((size_t)blockIdx.y * NPAIR + pairIdx) * (128 * 128)];
    #pragma unroll
    for (int mi = 0; mi < 2; mi++) {
        const int rr = ibase + 16 * mi + g;
        #pragma unroll
        for (int ni = 0; ni < 8; ni++) {
            const int cc = lbase + 8 * ni + 2 * t4;
            float2 v0 = make_float2(c[mi][ni][0] * sc, c[mi][ni][1] * sc);
            float2 v1 = make_float2(c[mi][ni][2] * sc, c[mi][ni][3] * sc);
            *(float2*)&dst[(size_t)rr * 128 + cc]       = v0;
            *(float2*)&dst[(size_t)(rr + 8) * 128 + cc] = v1;
        }
    }
}

// ---------------------------------------------------------------------------
// Kernel R: reduce 8 split-partials, write M tile + mirrored tile.
// grid = 9 pairs * 4 row-quarters per group.
// ---------------------------------------------------------------------------
__global__ void __launch_bounds__(256) kernelR(int pairBase) {
    __shared__ float ts[32][133];

    const int tid  = threadIdx.x;
    const int tile = pairBase + (blockIdx.x >> 2);
    const int q    = blockIdx.x & 3;
    int tr, tc; pair_from_idx(tile, tr, tc);
    const int i0 = tr * 128 + q * 32;
    const int l0 = tc * 128;

    for (int e = tid; e < 32 * 128; e += 256) {
        const int r = e >> 7, c = e & 127;
        float v = 0.f;
        #pragma unroll
        for (int s = 0; s < NSPLIT; s++)
            v += g_Mp[((size_t)s * NPAIR + tile) * (128 * 128) + (size_t)(q * 32 + r) * 128 + c];
        ts[r][c] = v;
    }
    __syncthreads();

    for (int e = tid; e < 32 * 128; e += 256) {
        const int r = e >> 7, c = e & 127;
        g_M[(size_t)(i0 + r) * KH + l0 + c] = ts[r][c];
    }
    if (tr != tc) {
        for (int e = tid; e < 128 * 32; e += 256) {
            const int lr = e >> 5, kc = e & 31;
            g_M[(size_t)(l0 + lr) * KH + i0 + kc] = ts[kc][lr];
        }
    }
}

// ---------------------------------------------------------------------------
// Kernel C: A[d,k,l] = M[k,l] * w[k,d] * w[l,d]  (256 MB store-bound).
// Full grid each launch; early-exit blocks whose M-tile pair is not in `group`.
// ---------------------------------------------------------------------------
#define C_KT 8
#define C_LT 128
#define C_WPAD 132

__global__ void __launch_bounds__(256, 8) kernelC(const float* __restrict__ w,
                                                  float* __restrict__ out,
                                                  int group) {
    const int l0  = blockIdx.x * C_LT;
    const int k0  = blockIdx.y * C_KT;
    {
        const int kt = k0 >> 7, lt = blockIdx.x;
        const int tr = kt < lt ? kt : lt;
        const int tc = kt < lt ? lt : kt;
        const int p  = idx_from_pair(tr, tc);
        if ((p / 9) != group) return;
    }

    __shared__ float wld[32][C_WPAD];
    __shared__ float Ms[C_KT][C_LT];
    __shared__ float wks[DIN][C_KT + 1];

    const int tid = threadIdx.x;

    for (int i = tid; i < C_KT * C_LT; i += 256) {
        const int kk = i >> 7, li = i & 127;
        Ms[kk][li] = g_M[(size_t)(k0 + kk) * KH + l0 + li];
    }
    for (int i = tid; i < C_KT * DIN; i += 256) {
        const int kk = i >> 6, d = i & 63;
        wks[d][kk] = w[(size_t)(k0 + kk) * DIN + d];
    }

    const int j     = tid >> 5;
    const int lane4 = (tid & 31) * 4;

    float4 M4;
    const size_t base = (size_t)(k0 + j) * KH + l0 + lane4;

    #pragma unroll
    for (int h = 0; h < 2; h++) {
        __syncthreads();
        for (int i = tid; i < 32 * C_LT; i += 256) {
            const int li = i >> 5, d = i & 31;
            wld[d][li] = w[(size_t)(l0 + li) * DIN + h * 32 + d];
        }
        __syncthreads();
        if (h == 0) M4 = *(const float4*)&Ms[j][lane4];

        #pragma unroll 8
        for (int dd = 0; dd < 32; dd++) {
            const int d = h * 32 + dd;
            const float wk  = wks[d][j];
            const float4 wl = *(const float4*)&wld[dd][lane4];
            float4 o;
            o.x = (M4.x * wk) * wl.x;
            o.y = (M4.y * wk) * wl.y;
            o.z = (M4.z * wk) * wl.z;
            o.w = (M4.w * wk) * wl.w;
            __stcs((float4*)&out[(size_t)d * (size_t)(KH * KH) + base], o);
        }
    }
}

// ---------------------------------------------------------------------------
// Launch: fork-join pipeline. Group 0's B/R on the main stream, groups 1..3 on
// a side stream overlapped with C of earlier groups. Lazily-created stream and
// events (first call is the eager correctness run, outside capture).
// ---------------------------------------------------------------------------
extern "C" void kernel_launch(void* const* d_in, const int* in_sizes, int n_in,
                              void* d_out, int out_size) {
    (void)in_sizes; (void)n_in; (void)out_size;
    const float* x = (const float*)d_in[0];
    const float* w = (const float*)d_in[1];
    const float* b = (const float*)d_in[2];
    float* out = (float*)d_out;

    static cudaStream_t s1 = nullptr;
    static cudaEvent_t  evFork = nullptr;
    static cudaEvent_t  evSide[NGRP - 1];
    if (s1 == nullptr) {
        cudaStreamCreateWithFlags(&s1, cudaStreamNonBlocking);
        cudaEventCreateWithFlags(&evFork, cudaEventDisableTiming);
        for (int i = 0; i < NGRP - 1; i++)
            cudaEventCreateWithFlags(&evSide[i], cudaEventDisableTiming);
    }
    const cudaStream_t s0 = (cudaStream_t)0;

    kernelA<<<dim3(KH / A_KT, N_OBS / A_NC), 256, 0, s0>>>(x, w, b);

    // group 0 on main stream
    kernelB_f16<<<dim3(9, NSPLIT), 256, 0, s0>>>(0);
    kernelR<<<9 * 4, 256, 0, s0>>>(0);
    cudaEventRecord(evFork, s0);

    // groups 1..3 on side stream (forked after group 0's R)
    cudaStreamWaitEvent(s1, evFork, 0);
    for (int g = 1; g < NGRP; g++) {
        kernelB_f16<<<dim3(9, NSPLIT), 256, 0, s1>>>(g * 9);
        kernelR<<<9 * 4, 256, 0, s1>>>(g * 9);
        cudaEventRecord(evSide[g - 1], s1);
    }

    // C groups on main stream, overlapped with side-stream B/R
    kernelC<<<dim3(KH / C_LT, KH / C_KT), 256, 0, s0>>>(w, out, 0);
    for (int g = 1; g < NGRP; g++) {
        cudaStreamWaitEvent(s0, evSide[g - 1], 0);
        kernelC<<<dim3(KH / C_LT, KH / C_KT), 256, 0, s0>>>(w, out, g);
    }
}

// round 9
// speedup vs baseline: 1.8230x; 1.8230x over previous
#include <cuda_runtime.h>
#include <cuda_fp16.h>
#include <cstdint>

#define N_OBS 2048
#define KH    1024
#define DIN   64
#define NTILE 8          // KH / 128
#define NPAIR 36         // upper-triangle tile pairs
#define NSPLIT 8         // split-K factor for kernelB

// Scratch (device globals: allocation-free per harness rules)
__device__ __half g_sT[KH * N_OBS];                  // 4 MB: sin activations fp16, (k, n)
__device__ float  g_M[KH * KH];                      // 4 MB: full symmetric Gram
__device__ float  g_Mp[NSPLIT * NPAIR * 128 * 128];  // 18.9 MB: per-(split,tile) partials

// ---------------------------------------------------------------------------
// Helpers (compute_103-portable)
// ---------------------------------------------------------------------------
__device__ __forceinline__ void pair_from_idx(int idx, int& tr, int& tc) {
    int t = 0, rem = idx;
    while (rem >= NTILE - t) { rem -= NTILE - t; t++; }
    tr = t; tc = t + rem;
}
__device__ __forceinline__ uint32_t smem_u32(const void* p) {
    uint32_t a;
    asm("{ .reg .u64 t; cvta.to.shared.u64 t, %1; cvt.u32.u64 %0, t; }" : "=r"(a) : "l"(p));
    return a;
}
__device__ __forceinline__ void cp_async16(uint32_t dst, const void* src) {
    asm volatile("cp.async.cg.shared.global [%0], [%1], 16;" :: "r"(dst), "l"(src));
}
#define CP_COMMIT() asm volatile("cp.async.commit_group;" ::: "memory")
#define CP_WAIT1()  asm volatile("cp.async.wait_group 1;" ::: "memory")
#define CP_WAIT0()  asm volatile("cp.async.wait_group 0;" ::: "memory")

__device__ __forceinline__ void ldmatrix_x4(uint32_t* r, uint32_t addr) {
    asm volatile("ldmatrix.sync.aligned.m8n8.x4.shared.b16 {%0,%1,%2,%3}, [%4];"
                 : "=r"(r[0]), "=r"(r[1]), "=r"(r[2]), "=r"(r[3]) : "r"(addr));
}
__device__ __forceinline__ void mma_f16(float* c, const uint32_t* a, const uint32_t* b) {
    asm volatile(
        "mma.sync.aligned.m16n8k16.row.col.f32.f16.f16.f32 "
        "{%0,%1,%2,%3}, {%4,%5,%6,%7}, {%8,%9}, {%0,%1,%2,%3};"
        : "+f"(c[0]), "+f"(c[1]), "+f"(c[2]), "+f"(c[3])
        : "r"(a[0]), "r"(a[1]), "r"(a[2]), "r"(a[3]), "r"(b[0]), "r"(b[1]));
}

// ---------------------------------------------------------------------------
// Kernel A: g_sT[k][n] = half( __sinf( dot(x[n,:], w[k,:]) + b[k] ) )
// grid = (KH/32, N_OBS/128), 256 threads. Warp: 4 k-rows x 128 n.
// w staged transposed: 4 per-warp k-values at fixed d = one broadcast LDS.128.
// ---------------------------------------------------------------------------
#define A_KT 32
#define A_NC 128
#define A_XPAD 132   // 132*4 = 528 B row stride, 16B-aligned
#define A_WPAD 36    // 36*4  = 144 B row stride, 16B-aligned

__global__ void __launch_bounds__(256) kernelA(const float* __restrict__ x,
                                               const float* __restrict__ w,
                                               const float* __restrict__ b) {
    __shared__ __align__(16) float xsT[DIN][A_XPAD];    // 33.8 KB  xsT[d][n_local]
    __shared__ __align__(16) float wksT[DIN][A_WPAD];   // 9.2 KB   wksT[d][k_local]

    const int tid = threadIdx.x;
    const int k0  = blockIdx.x * A_KT;
    const int n0  = blockIdx.y * A_NC;

    for (int i = tid; i < A_NC * DIN; i += 256) {
        const int n = i >> 6, d = i & 63;
        xsT[d][n] = x[(size_t)(n0 + n) * DIN + d];
    }
    for (int i = tid; i < A_KT * DIN; i += 256) {
        const int k = i >> 6, d = i & 63;
        wksT[d][k] = w[(size_t)(k0 + k) * DIN + d];
    }
    __syncthreads();

    const int warp  = tid >> 5;
    const int lane4 = (tid & 31) * 4;
    const int r0 = warp * 4;

    float acc[4][4];
    #pragma unroll
    for (int r = 0; r < 4; r++)
        #pragma unroll
        for (int c = 0; c < 4; c++) acc[r][c] = 0.f;

    #pragma unroll 8
    for (int d = 0; d < DIN; d++) {
        const float4 xv = *(const float4*)&xsT[d][lane4];    // LDS.128 conflict-free
        const float4 wv = *(const float4*)&wksT[d][r0];      // LDS.128 broadcast
        acc[0][0] += wv.x * xv.x; acc[0][1] += wv.x * xv.y;
        acc[0][2] += wv.x * xv.z; acc[0][3] += wv.x * xv.w;
        acc[1][0] += wv.y * xv.x; acc[1][1] += wv.y * xv.y;
        acc[1][2] += wv.y * xv.z; acc[1][3] += wv.y * xv.w;
        acc[2][0] += wv.z * xv.x; acc[2][1] += wv.z * xv.y;
        acc[2][2] += wv.z * xv.z; acc[2][3] += wv.z * xv.w;
        acc[3][0] += wv.w * xv.x; acc[3][1] += wv.w * xv.y;
        acc[3][2] += wv.w * xv.z; acc[3][3] += wv.w * xv.w;
    }

    #pragma unroll
    for (int r = 0; r < 4; r++) {
        const float bv = b[k0 + r0 + r];
        __half2 p0 = __floats2half2_rn(__sinf(acc[r][0] + bv), __sinf(acc[r][1] + bv));
        __half2 p1 = __floats2half2_rn(__sinf(acc[r][2] + bv), __sinf(acc[r][3] + bv));
        uint2 u;
        u.x = *(uint32_t*)&p0;
        u.y = *(uint32_t*)&p1;
        *(uint2*)&g_sT[(size_t)(k0 + r0 + r) * N_OBS + n0 + lane4] = u;
    }
}

// ---------------------------------------------------------------------------
// Kernel B: partial Gram via fp16 mma.m16n8k16 + ldmatrix, cp.async dbl-buffer.
// grid = (36 pairs, 8 splits), 256 threads (8 warps 4x2, warp tile 32x64).
// B-fragments loaded one ldmatrix group at a time (low live regs -> 3 CTAs/SM).
// ---------------------------------------------------------------------------
#define B_ROWB  80                    // 64B data + 16B pad
#define B_OPB   (128 * B_ROWB)        // 10240 B per operand tile
#define B_BUF   (2 * B_OPB)           // one (A,B) buffer pair
#define B_SMEMB (2 * B_BUF)           // 40960 B double-buffered
#define B_NCH   8                     // 256 n per CTA / 32 per chunk

__global__ void __launch_bounds__(256, 3) kernelB_f16() {
    __shared__ __align__(16) char sm[B_SMEMB];

    const int tid = threadIdx.x;
    const int wid = tid >> 5;
    const int lid = tid & 31;
    const int g   = lid >> 2;
    const int t4  = lid & 3;

    int tr, tc; pair_from_idx(blockIdx.x, tr, tc);
    const int i0 = tr * 128, l0 = tc * 128;
    const bool diag = (tr == tc);
    const int ops  = diag ? 1 : 2;
    const int nb   = blockIdx.y * (N_OBS / NSPLIT);

    const uint32_t sb = smem_u32(sm);
    const int wr = wid & 3;            // i offset wr*32
    const int wc = wid >> 2;           // l offset wc*64
    const int ibase = wr * 32, lbase = wc * 64;

    float c[2][8][4];
    #pragma unroll
    for (int mi = 0; mi < 2; mi++)
        #pragma unroll
        for (int ni = 0; ni < 8; ni++)
            #pragma unroll
            for (int t = 0; t < 4; t++) c[mi][ni][t] = 0.f;

    auto stage = [&](int ch, int buf) {
        const int n0 = nb + ch * 32;
        const int tot = ops << 9;                        // 512 cp.async per operand
        for (int e = tid; e < tot; e += 256) {
            const int op  = e >> 9;
            const int idx = e & 511;
            const int row = idx >> 2;
            const int c16 = idx & 3;
            const int grow = (op ? l0 : i0) + row;
            cp_async16(sb + (uint32_t)(buf * B_BUF + op * B_OPB + row * B_ROWB + c16 * 16),
                       &g_sT[(size_t)grow * N_OBS + n0 + c16 * 8]);
        }
    };

    const uint32_t aOff0 = (uint32_t)((ibase + (lid & 15)) * B_ROWB + (lid >> 4) * 16);
    const uint32_t bRow  = (uint32_t)(lbase + ((lid >> 4) << 3) + (lid & 7));
    const uint32_t bOff0 = bRow * B_ROWB + ((lid >> 3) & 1) * 16;

    stage(0, 0);
    CP_COMMIT();

    for (int ch = 0; ch < B_NCH; ch++) {
        const int buf = ch & 1;
        if (ch + 1 < B_NCH) { stage(ch + 1, buf ^ 1); CP_COMMIT(); CP_WAIT1(); }
        else                { CP_WAIT0(); }
        __syncthreads();

        const uint32_t aBase = sb + buf * B_BUF;
        const uint32_t bBase = diag ? aBase : aBase + B_OPB;

        #pragma unroll
        for (int ks = 0; ks < 2; ks++) {                 // two k16 steps per 32-n chunk
            uint32_t a[2][4];
            #pragma unroll
            for (int mi = 0; mi < 2; mi++)
                ldmatrix_x4(a[mi], aBase + aOff0 + (uint32_t)(mi * 16 * B_ROWB + ks * 32));
            #pragma unroll
            for (int p = 0; p < 4; p++) {                // one B-group at a time
                uint32_t bb[4];
                ldmatrix_x4(bb, bBase + bOff0 + (uint32_t)(p * 16 * B_ROWB + ks * 32));
                #pragma unroll
                for (int mi = 0; mi < 2; mi++) {
                    mma_f16(c[mi][2 * p],     a[mi], &bb[0]);
                    mma_f16(c[mi][2 * p + 1], a[mi], &bb[2]);
                }
            }
        }
        __syncthreads();                                 // reads done before buf reuse
    }

    const float sc = (2.0f / (float)KH) / (float)N_OBS;
    float* dst = &g_Mp[((size_t)blockIdx.y * NPAIR + blockIdx.x) * (128 * 128)];
    #pragma unroll
    for (int mi = 0; mi < 2; mi++) {
        const int rr = ibase + 16 * mi + g;
        #pragma unroll
        for (int ni = 0; ni < 8; ni++) {
            const int cc = lbase + 8 * ni + 2 * t4;
            float2 v0 = make_float2(c[mi][ni][0] * sc, c[mi][ni][1] * sc);
            float2 v1 = make_float2(c[mi][ni][2] * sc, c[mi][ni][3] * sc);
            *(float2*)&dst[(size_t)rr * 128 + cc]       = v0;
            *(float2*)&dst[(size_t)(rr + 8) * 128 + cc] = v1;
        }
    }
}

// ---------------------------------------------------------------------------
// Kernel R: reduce 8 split-partials, write M tile + mirror.
// Global accesses vectorized (float4); smem side scalar (133-stride keeps the
// transposed reads conflict-free and avoids float4-on-odd-stride misalignment).
// grid = 36 tiles * 4 row-quarters, 256 threads.
// ---------------------------------------------------------------------------
__global__ void __launch_bounds__(256) kernelR() {
    __shared__ float ts[32][133];

    const int tid  = threadIdx.x;
    const int tile = blockIdx.x >> 2;
    const int q    = blockIdx.x & 3;
    int tr, tc; pair_from_idx(tile, tr, tc);
    const int i0 = tr * 128 + q * 32;
    const int l0 = tc * 128;

    // 32x128 quarter = 1024 float4 loads per split; scalar stores into ts
    for (int e = tid; e < 32 * 32; e += 256) {
        const int r = e >> 5, c4 = (e & 31) * 4;
        float4 v = make_float4(0.f, 0.f, 0.f, 0.f);
        #pragma unroll
        for (int s = 0; s < NSPLIT; s++) {
            const float4 p = *(const float4*)
                &g_Mp[((size_t)s * NPAIR + tile) * (128 * 128) + (size_t)(q * 32 + r) * 128 + c4];
            v.x += p.x; v.y += p.y; v.z += p.z; v.w += p.w;
        }
        ts[r][c4 + 0] = v.x; ts[r][c4 + 1] = v.y;
        ts[r][c4 + 2] = v.z; ts[r][c4 + 3] = v.w;
    }
    __syncthreads();

    // normal write: scalar LDS, float4 STG (coalesced)
    for (int e = tid; e < 32 * 32; e += 256) {
        const int r = e >> 5, c4 = (e & 31) * 4;
        float4 v;
        v.x = ts[r][c4 + 0]; v.y = ts[r][c4 + 1];
        v.z = ts[r][c4 + 2]; v.w = ts[r][c4 + 3];
        *(float4*)&g_M[(size_t)(i0 + r) * KH + l0 + c4] = v;
    }
    // mirrored write: transposed smem reads (conflict-free via 133 stride)
    if (tr != tc) {
        for (int e = tid; e < 128 * 32; e += 256) {
            const int lr = e >> 5, kc = e & 31;
            g_M[(size_t)(l0 + lr) * KH + i0 + kc] = ts[kc][lr];
        }
    }
}

// ---------------------------------------------------------------------------
// Kernel C: A[d,k,l] = M[k,l] * w[k,d] * w[l,d]  (256 MB store-bound)
// grid = (KH/128, KH/8), 256 threads, 8 CTAs/SM. At the HBM-write wall.
// ---------------------------------------------------------------------------
#define C_KT 8
#define C_LT 128
#define C_WPAD 132

__global__ void __launch_bounds__(256, 8) kernelC(const float* __restrict__ w,
                                                  float* __restrict__ out) {
    __shared__ __align__(16) float wld[32][C_WPAD];     // 16.9 KB
    __shared__ __align__(16) float Ms[C_KT][C_LT];      // 4 KB
    __shared__ float wks[DIN][C_KT + 1];                // 2.3 KB

    const int tid = threadIdx.x;
    const int l0  = blockIdx.x * C_LT;
    const int k0  = blockIdx.y * C_KT;

    for (int i = tid; i < C_KT * C_LT; i += 256) {
        const int kk = i >> 7, li = i & 127;
        Ms[kk][li] = g_M[(size_t)(k0 + kk) * KH + l0 + li];
    }
    for (int i = tid; i < C_KT * DIN; i += 256) {
        const int kk = i >> 6, d = i & 63;
        wks[d][kk] = w[(size_t)(k0 + kk) * DIN + d];
    }

    const int j     = tid >> 5;
    const int lane4 = (tid & 31) * 4;

    float4 M4;
    const size_t base = (size_t)(k0 + j) * KH + l0 + lane4;

    #pragma unroll
    for (int h = 0; h < 2; h++) {
        __syncthreads();
        for (int i = tid; i < 32 * C_LT; i += 256) {
            const int li = i >> 5, d = i & 31;
            wld[d][li] = w[(size_t)(l0 + li) * DIN + h * 32 + d];
        }
        __syncthreads();
        if (h == 0) M4 = *(const float4*)&Ms[j][lane4];

        #pragma unroll 8
        for (int dd = 0; dd < 32; dd++) {
            const int d = h * 32 + dd;
            const float wk  = wks[d][j];
            const float4 wl = *(const float4*)&wld[dd][lane4];
            float4 o;
            o.x = (M4.x * wk) * wl.x;
            o.y = (M4.y * wk) * wl.y;
            o.z = (M4.z * wk) * wl.z;
            o.w = (M4.w * wk) * wl.w;
            __stcs((float4*)&out[(size_t)d * (size_t)(KH * KH) + base], o);
        }
    }
}

// ---------------------------------------------------------------------------
extern "C" void kernel_launch(void* const* d_in, const int* in_sizes, int n_in,
                              void* d_out, int out_size) {
    (void)in_sizes; (void)n_in; (void)out_size;
    const float* x = (const float*)d_in[0];
    const float* w = (const float*)d_in[1];
    const float* b = (const float*)d_in[2];
    float* out = (float*)d_out;

    kernelA<<<dim3(KH / A_KT, N_OBS / A_NC), 256>>>(x, w, b);
    kernelB_f16<<<dim3(NPAIR, NSPLIT), 256>>>();
    kernelR<<<NPAIR * 4, 256>>>();
    kernelC<<<dim3(KH / C_LT, KH / C_KT), 256>>>(w, out);
}

// round 10
// speedup vs baseline: 1.8602x; 1.0204x over previous
#include <cuda_runtime.h>
#include <cuda_fp16.h>
#include <cstdint>

#define N_OBS 2048
#define KH    1024
#define DIN   64
#define NTILE 8          // KH / 128
#define NPAIR 36         // upper-triangle tile pairs
#define NSPLIT 8         // split-K factor for kernelB

// Scratch (device globals: allocation-free per harness rules)
__device__ __half g_sT[KH * N_OBS];                  // 4 MB: sin activations fp16, (k, n)
__device__ float  g_Mp[NSPLIT * NPAIR * 128 * 128];  // 18.9 MB: per-(split,tile) partials (L2-resident)

// ---------------------------------------------------------------------------
// Helpers (compute_103-portable)
// ---------------------------------------------------------------------------
__device__ __forceinline__ void pair_from_idx(int idx, int& tr, int& tc) {
    int t = 0, rem = idx;
    while (rem >= NTILE - t) { rem -= NTILE - t; t++; }
    tr = t; tc = t + rem;
}
__device__ __forceinline__ int idx_from_pair(int tr, int tc) {   // tr <= tc
    return tr * NTILE - (tr * (tr - 1)) / 2 + (tc - tr);
}
__device__ __forceinline__ uint32_t smem_u32(const void* p) {
    uint32_t a;
    asm("{ .reg .u64 t; cvta.to.shared.u64 t, %1; cvt.u32.u64 %0, t; }" : "=r"(a) : "l"(p));
    return a;
}
__device__ __forceinline__ void cp_async16(uint32_t dst, const void* src) {
    asm volatile("cp.async.cg.shared.global [%0], [%1], 16;" :: "r"(dst), "l"(src));
}
#define CP_COMMIT() asm volatile("cp.async.commit_group;" ::: "memory")
#define CP_WAIT1()  asm volatile("cp.async.wait_group 1;" ::: "memory")
#define CP_WAIT0()  asm volatile("cp.async.wait_group 0;" ::: "memory")

__device__ __forceinline__ void ldmatrix_x4(uint32_t* r, uint32_t addr) {
    asm volatile("ldmatrix.sync.aligned.m8n8.x4.shared.b16 {%0,%1,%2,%3}, [%4];"
                 : "=r"(r[0]), "=r"(r[1]), "=r"(r[2]), "=r"(r[3]) : "r"(addr));
}
__device__ __forceinline__ void mma_f16(float* c, const uint32_t* a, const uint32_t* b) {
    asm volatile(
        "mma.sync.aligned.m16n8k16.row.col.f32.f16.f16.f32 "
        "{%0,%1,%2,%3}, {%4,%5,%6,%7}, {%8,%9}, {%0,%1,%2,%3};"
        : "+f"(c[0]), "+f"(c[1]), "+f"(c[2]), "+f"(c[3])
        : "r"(a[0]), "r"(a[1]), "r"(a[2]), "r"(a[3]), "r"(b[0]), "r"(b[1]));
}

// ---------------------------------------------------------------------------
// Kernel A: g_sT[k][n] = half( __sinf( dot(x[n,:], w[k,:]) + b[k] ) )
// grid = (KH/32, N_OBS/128), 256 threads. Warp: 4 k-rows x 128 n.
// ---------------------------------------------------------------------------
#define A_KT 32
#define A_NC 128
#define A_XPAD 132   // 528 B row stride, 16B-aligned
#define A_WPAD 36    // 144 B row stride, 16B-aligned

__global__ void __launch_bounds__(256) kernelA(const float* __restrict__ x,
                                               const float* __restrict__ w,
                                               const float* __restrict__ b) {
    __shared__ __align__(16) float xsT[DIN][A_XPAD];    // 33.8 KB  xsT[d][n_local]
    __shared__ __align__(16) float wksT[DIN][A_WPAD];   // 9.2 KB   wksT[d][k_local]

    const int tid = threadIdx.x;
    const int k0  = blockIdx.x * A_KT;
    const int n0  = blockIdx.y * A_NC;

    for (int i = tid; i < A_NC * DIN; i += 256) {
        const int n = i >> 6, d = i & 63;
        xsT[d][n] = x[(size_t)(n0 + n) * DIN + d];
    }
    for (int i = tid; i < A_KT * DIN; i += 256) {
        const int k = i >> 6, d = i & 63;
        wksT[d][k] = w[(size_t)(k0 + k) * DIN + d];
    }
    __syncthreads();

    const int warp  = tid >> 5;
    const int lane4 = (tid & 31) * 4;
    const int r0 = warp * 4;

    float acc[4][4];
    #pragma unroll
    for (int r = 0; r < 4; r++)
        #pragma unroll
        for (int c = 0; c < 4; c++) acc[r][c] = 0.f;

    #pragma unroll 8
    for (int d = 0; d < DIN; d++) {
        const float4 xv = *(const float4*)&xsT[d][lane4];    // LDS.128 conflict-free
        const float4 wv = *(const float4*)&wksT[d][r0];      // LDS.128 broadcast
        acc[0][0] += wv.x * xv.x; acc[0][1] += wv.x * xv.y;
        acc[0][2] += wv.x * xv.z; acc[0][3] += wv.x * xv.w;
        acc[1][0] += wv.y * xv.x; acc[1][1] += wv.y * xv.y;
        acc[1][2] += wv.y * xv.z; acc[1][3] += wv.y * xv.w;
        acc[2][0] += wv.z * xv.x; acc[2][1] += wv.z * xv.y;
        acc[2][2] += wv.z * xv.z; acc[2][3] += wv.z * xv.w;
        acc[3][0] += wv.w * xv.x; acc[3][1] += wv.w * xv.y;
        acc[3][2] += wv.w * xv.z; acc[3][3] += wv.w * xv.w;
    }

    #pragma unroll
    for (int r = 0; r < 4; r++) {
        const float bv = b[k0 + r0 + r];
        __half2 p0 = __floats2half2_rn(__sinf(acc[r][0] + bv), __sinf(acc[r][1] + bv));
        __half2 p1 = __floats2half2_rn(__sinf(acc[r][2] + bv), __sinf(acc[r][3] + bv));
        uint2 u;
        u.x = *(uint32_t*)&p0;
        u.y = *(uint32_t*)&p1;
        *(uint2*)&g_sT[(size_t)(k0 + r0 + r) * N_OBS + n0 + lane4] = u;
    }
}

// ---------------------------------------------------------------------------
// Kernel B: partial Gram via fp16 mma.m16n8k16 + ldmatrix, cp.async dbl-buffer.
// grid = (36 pairs, 8 splits), 256 threads (8 warps 4x2, warp tile 32x64).
// ---------------------------------------------------------------------------
#define B_ROWB  80                    // 64B data + 16B pad
#define B_OPB   (128 * B_ROWB)        // 10240 B per operand tile
#define B_BUF   (2 * B_OPB)
#define B_SMEMB (2 * B_BUF)           // 40960 B double-buffered
#define B_NCH   8                     // 256 n per CTA / 32 per chunk

__global__ void __launch_bounds__(256, 3) kernelB_f16() {
    __shared__ __align__(16) char sm[B_SMEMB];

    const int tid = threadIdx.x;
    const int wid = tid >> 5;
    const int lid = tid & 31;
    const int g   = lid >> 2;
    const int t4  = lid & 3;

    int tr, tc; pair_from_idx(blockIdx.x, tr, tc);
    const int i0 = tr * 128, l0 = tc * 128;
    const bool diag = (tr == tc);
    const int ops  = diag ? 1 : 2;
    const int nb   = blockIdx.y * (N_OBS / NSPLIT);

    const uint32_t sb = smem_u32(sm);
    const int wr = wid & 3;
    const int wc = wid >> 2;
    const int ibase = wr * 32, lbase = wc * 64;

    float c[2][8][4];
    #pragma unroll
    for (int mi = 0; mi < 2; mi++)
        #pragma unroll
        for (int ni = 0; ni < 8; ni++)
            #pragma unroll
            for (int t = 0; t < 4; t++) c[mi][ni][t] = 0.f;

    auto stage = [&](int ch, int buf) {
        const int n0 = nb + ch * 32;
        const int tot = ops << 9;
        for (int e = tid; e < tot; e += 256) {
            const int op  = e >> 9;
            const int idx = e & 511;
            const int row = idx >> 2;
            const int c16 = idx & 3;
            const int grow = (op ? l0 : i0) + row;
            cp_async16(sb + (uint32_t)(buf * B_BUF + op * B_OPB + row * B_ROWB + c16 * 16),
                       &g_sT[(size_t)grow * N_OBS + n0 + c16 * 8]);
        }
    };

    const uint32_t aOff0 = (uint32_t)((ibase + (lid & 15)) * B_ROWB + (lid >> 4) * 16);
    const uint32_t bRow  = (uint32_t)(lbase + ((lid >> 4) << 3) + (lid & 7));
    const uint32_t bOff0 = bRow * B_ROWB + ((lid >> 3) & 1) * 16;

    stage(0, 0);
    CP_COMMIT();

    for (int ch = 0; ch < B_NCH; ch++) {
        const int buf = ch & 1;
        if (ch + 1 < B_NCH) { stage(ch + 1, buf ^ 1); CP_COMMIT(); CP_WAIT1(); }
        else                { CP_WAIT0(); }
        __syncthreads();

        const uint32_t aBase = sb + buf * B_BUF;
        const uint32_t bBase = diag ? aBase : aBase + B_OPB;

        #pragma unroll
        for (int ks = 0; ks < 2; ks++) {
            uint32_t a[2][4];
            #pragma unroll
            for (int mi = 0; mi < 2; mi++)
                ldmatrix_x4(a[mi], aBase + aOff0 + (uint32_t)(mi * 16 * B_ROWB + ks * 32));
            #pragma unroll
            for (int p = 0; p < 4; p++) {
                uint32_t bb[4];
                ldmatrix_x4(bb, bBase + bOff0 + (uint32_t)(p * 16 * B_ROWB + ks * 32));
                #pragma unroll
                for (int mi = 0; mi < 2; mi++) {
                    mma_f16(c[mi][2 * p],     a[mi], &bb[0]);
                    mma_f16(c[mi][2 * p + 1], a[mi], &bb[2]);
                }
            }
        }
        __syncthreads();
    }

    const float sc = (2.0f / (float)KH) / (float)N_OBS;
    float* dst = &g_Mp[((size_t)blockIdx.y * NPAIR + blockIdx.x) * (128 * 128)];
    #pragma unroll
    for (int mi = 0; mi < 2; mi++) {
        const int rr = ibase + 16 * mi + g;
        #pragma unroll
        for (int ni = 0; ni < 8; ni++) {
            const int cc = lbase + 8 * ni + 2 * t4;
            float2 v0 = make_float2(c[mi][ni][0] * sc, c[mi][ni][1] * sc);
            float2 v1 = make_float2(c[mi][ni][2] * sc, c[mi][ni][3] * sc);
            *(float2*)&dst[(size_t)rr * 128 + cc]       = v0;
            *(float2*)&dst[(size_t)(rr + 8) * 128 + cc] = v1;
        }
    }
}

// ---------------------------------------------------------------------------
// Kernel C (fused R): Ms tile reduced from the 8 split-partials in-prologue,
// then A[d,k,l] = Ms[k,l] * w[k,d] * w[l,d]. 256 MB store-bound.
// grid = (KH/128 l-tiles, KH/8 k-blocks), 256 threads, 8 CTAs/SM.
// ---------------------------------------------------------------------------
#define C_KT 8
#define C_LT 128
#define C_WPAD 132

__global__ void __launch_bounds__(256, 8) kernelC(const float* __restrict__ w,
                                                  float* __restrict__ out) {
    __shared__ __align__(16) float wld[32][C_WPAD];     // 16.9 KB
    __shared__ __align__(16) float Ms[C_KT][C_LT];      // 4 KB
    __shared__ float wks[DIN][C_KT + 1];                // 2.3 KB

    const int tid = threadIdx.x;
    const int lt  = blockIdx.x;
    const int l0  = lt * C_LT;
    const int k0  = blockIdx.y * C_KT;
    const int kt  = k0 >> 7;
    const int ko  = k0 & 127;                           // row offset inside k-tile

    // ---- fused reduction: Ms[kk][li] = sum_s Mp[s][pair] (transposed if kt>lt)
    if (kt <= lt) {
        const size_t pbase = (size_t)idx_from_pair(kt, lt) * (128 * 128);
        // rows ko..ko+7, all 128 cols; fully coalesced float4
        for (int e = tid; e < 256; e += 256) { }        // (no-op; keep structure simple)
        {
            const int kk  = tid >> 5;                   // 0..7
            const int li4 = (tid & 31) * 4;
            float4 v = make_float4(0.f, 0.f, 0.f, 0.f);
            #pragma unroll
            for (int s = 0; s < NSPLIT; s++) {
                const float4 p = *(const float4*)
                    &g_Mp[(size_t)s * NPAIR * (128 * 128) + pbase + (size_t)(ko + kk) * 128 + li4];
                v.x += p.x; v.y += p.y; v.z += p.z; v.w += p.w;
            }
            *(float4*)&Ms[kk][li4] = v;
        }
    } else {
        const size_t pbase = (size_t)idx_from_pair(lt, kt) * (128 * 128);
        // need Ms[kk][li] = S[li][ko+kk]: each thread sums a float4 along kk
        const int li = tid >> 1;                        // 0..127
        const int h  = tid & 1;                         // which half of the 8 kk cols
        float4 v = make_float4(0.f, 0.f, 0.f, 0.f);
        #pragma unroll
        for (int s = 0; s < NSPLIT; s++) {
            const float4 p = *(const float4*)
                &g_Mp[(size_t)s * NPAIR * (128 * 128) + pbase + (size_t)li * 128 + ko + h * 4];
            v.x += p.x; v.y += p.y; v.z += p.z; v.w += p.w;
        }
        Ms[h * 4 + 0][li] = v.x;
        Ms[h * 4 + 1][li] = v.y;
        Ms[h * 4 + 2][li] = v.z;
        Ms[h * 4 + 3][li] = v.w;
    }

    for (int i = tid; i < C_KT * DIN; i += 256) {
        const int kk = i >> 6, d = i & 63;
        wks[d][kk] = w[(size_t)(k0 + kk) * DIN + d];
    }

    const int j     = tid >> 5;
    const int lane4 = (tid & 31) * 4;

    float4 M4;
    const size_t base = (size_t)(k0 + j) * KH + l0 + lane4;

    #pragma unroll
    for (int h = 0; h < 2; h++) {
        __syncthreads();
        for (int i = tid; i < 32 * C_LT; i += 256) {
            const int li = i >> 5, d = i & 31;
            wld[d][li] = w[(size_t)(l0 + li) * DIN + h * 32 + d];
        }
        __syncthreads();
        if (h == 0) M4 = *(const float4*)&Ms[j][lane4];

        #pragma unroll 8
        for (int dd = 0; dd < 32; dd++) {
            const int d = h * 32 + dd;
            const float wk  = wks[d][j];
            const float4 wl = *(const float4*)&wld[dd][lane4];
            float4 o;
            o.x = (M4.x * wk) * wl.x;
            o.y = (M4.y * wk) * wl.y;
            o.z = (M4.z * wk) * wl.z;
            o.w = (M4.w * wk) * wl.w;
            __stcs((float4*)&out[(size_t)d * (size_t)(KH * KH) + base], o);
        }
    }
}

// ---------------------------------------------------------------------------
extern "C" void kernel_launch(void* const* d_in, const int* in_sizes, int n_in,
                              void* d_out, int out_size) {
    (void)in_sizes; (void)n_in; (void)out_size;
    const float* x = (const float*)d_in[0];
    const float* w = (const float*)d_in[1];
    const float* b = (const float*)d_in[2];
    float* out = (float*)d_out;

    kernelA<<<dim3(KH / A_KT, N_OBS / A_NC), 256>>>(x, w, b);
    kernelB_f16<<<dim3(NPAIR, NSPLIT), 256>>>();
    kernelC<<<dim3(KH / C_LT, KH / C_KT), 256>>>(w, out);
}

// round 11
// speedup vs baseline: 1.8935x; 1.0179x over previous
#include <cuda_runtime.h>
#include <cuda_fp16.h>
#include <cstdint>

#define N_OBS 2048
#define KH    1024
#define DIN   64
#define NTILE 8          // KH / 128
#define NPAIR 36         // upper-triangle tile pairs
#define NSPLIT 8         // split-K factor for kernelB

// Scratch (device globals: allocation-free per harness rules)
__device__ __half g_sT[KH * N_OBS];                  // 4 MB: sin activations fp16, (k, n)
__device__ float  g_Mp[NSPLIT * NPAIR * 128 * 128];  // 18.9 MB: per-(split,tile) partials (L2-resident)

// ---------------------------------------------------------------------------
// Helpers (compute_103-portable)
// ---------------------------------------------------------------------------
__device__ __forceinline__ void pair_from_idx(int idx, int& tr, int& tc) {
    int t = 0, rem = idx;
    while (rem >= NTILE - t) { rem -= NTILE - t; t++; }
    tr = t; tc = t + rem;
}
__device__ __forceinline__ int idx_from_pair(int tr, int tc) {   // tr <= tc
    return tr * NTILE - (tr * (tr - 1)) / 2 + (tc - tr);
}
__device__ __forceinline__ float to_tf32(float x) {
    float y; asm("cvt.rna.tf32.f32 %0, %1;" : "=f"(y) : "f"(x)); return y;
}
__device__ __forceinline__ uint32_t smem_u32(const void* p) {
    uint32_t a;
    asm("{ .reg .u64 t; cvta.to.shared.u64 t, %1; cvt.u32.u64 %0, t; }" : "=r"(a) : "l"(p));
    return a;
}
__device__ __forceinline__ void cp_async16(uint32_t dst, const void* src) {
    asm volatile("cp.async.cg.shared.global [%0], [%1], 16;" :: "r"(dst), "l"(src));
}
#define CP_COMMIT() asm volatile("cp.async.commit_group;" ::: "memory")
#define CP_WAIT1()  asm volatile("cp.async.wait_group 1;" ::: "memory")
#define CP_WAIT0()  asm volatile("cp.async.wait_group 0;" ::: "memory")

__device__ __forceinline__ void ldmatrix_x4(uint32_t* r, uint32_t addr) {
    asm volatile("ldmatrix.sync.aligned.m8n8.x4.shared.b16 {%0,%1,%2,%3}, [%4];"
                 : "=r"(r[0]), "=r"(r[1]), "=r"(r[2]), "=r"(r[3]) : "r"(addr));
}
__device__ __forceinline__ void mma_f16(float* c, const uint32_t* a, const uint32_t* b) {
    asm volatile(
        "mma.sync.aligned.m16n8k16.row.col.f32.f16.f16.f32 "
        "{%0,%1,%2,%3}, {%4,%5,%6,%7}, {%8,%9}, {%0,%1,%2,%3};"
        : "+f"(c[0]), "+f"(c[1]), "+f"(c[2]), "+f"(c[3])
        : "r"(a[0]), "r"(a[1]), "r"(a[2]), "r"(a[3]), "r"(b[0]), "r"(b[1]));
}
__device__ __forceinline__ void mma_tf32(float* c, const uint32_t* a, const uint32_t* b) {
    asm volatile(
        "mma.sync.aligned.m16n8k8.row.col.f32.tf32.tf32.f32 "
        "{%0,%1,%2,%3}, {%4,%5,%6,%7}, {%8,%9}, {%0,%1,%2,%3};"
        : "+f"(c[0]), "+f"(c[1]), "+f"(c[2]), "+f"(c[3])
        : "r"(a[0]), "r"(a[1]), "r"(a[2]), "r"(a[3]), "r"(b[0]), "r"(b[1]));
}

// ---------------------------------------------------------------------------
// Kernel A (tensor-core, 3xTF32): g_sT[k][n] = half(__sinf(x@w.T + b))
// Exact-as-fp32 GEMM: z = xhi*whi + xhi*wlo + xlo*whi (lo.lo term ~2^-22, dropped).
// grid = (KH/128, N_OBS/128) = (8,16), 256 threads, warp grid 4(k) x 2(n),
// warp tile 32k x 64n. d staged in 4 chunks of 16.
// ---------------------------------------------------------------------------
#define AT_DC  16                 // d per chunk
#define AT_RP  18                 // smem row stride (16 + 2 pad)

__global__ void __launch_bounds__(256) kernelA_tc(const float* __restrict__ x,
                                                  const float* __restrict__ w,
                                                  const float* __restrict__ b) {
    __shared__ float whi[128][AT_RP], wlo[128][AT_RP];   // 18.4 KB
    __shared__ float xhi[128][AT_RP], xlo[128][AT_RP];   // 18.4 KB

    const int tid = threadIdx.x;
    const int wid = tid >> 5;
    const int lid = tid & 31;
    const int g   = lid >> 2;
    const int t4  = lid & 3;

    const int k0 = blockIdx.x * 128;
    const int n0 = blockIdx.y * 128;

    const int wr = wid & 3;             // k offset wr*32
    const int wc = wid >> 2;            // n offset wc*64
    const int ibase = wr * 32, nbase = wc * 64;

    float c[2][8][4];
    #pragma unroll
    for (int mi = 0; mi < 2; mi++)
        #pragma unroll
        for (int ni = 0; ni < 8; ni++)
            #pragma unroll
            for (int t = 0; t < 4; t++) c[mi][ni][t] = 0.f;

    for (int dc = 0; dc < DIN; dc += AT_DC) {
        __syncthreads();                 // previous chunk's reads done
        for (int e = tid; e < 128 * AT_DC; e += 256) {
            const int row = e >> 4, col = e & 15;
            const float wv = w[(size_t)(k0 + row) * DIN + dc + col];
            const float wh = to_tf32(wv);
            whi[row][col] = wh;
            wlo[row][col] = to_tf32(wv - wh);
            const float xv = x[(size_t)(n0 + row) * DIN + dc + col];
            const float xh = to_tf32(xv);
            xhi[row][col] = xh;
            xlo[row][col] = to_tf32(xv - xh);
        }
        __syncthreads();

        #pragma unroll
        for (int ks = 0; ks < AT_DC / 8; ks++) {
            const int kb = ks * 8 + t4;
            uint32_t ah[2][4], al[2][4];
            #pragma unroll
            for (int mi = 0; mi < 2; mi++) {
                const int r = ibase + 16 * mi + g;
                ah[mi][0] = __float_as_uint(whi[r][kb]);
                ah[mi][1] = __float_as_uint(whi[r + 8][kb]);
                ah[mi][2] = __float_as_uint(whi[r][kb + 4]);
                ah[mi][3] = __float_as_uint(whi[r + 8][kb + 4]);
                al[mi][0] = __float_as_uint(wlo[r][kb]);
                al[mi][1] = __float_as_uint(wlo[r + 8][kb]);
                al[mi][2] = __float_as_uint(wlo[r][kb + 4]);
                al[mi][3] = __float_as_uint(wlo[r + 8][kb + 4]);
            }
            #pragma unroll
            for (int ni = 0; ni < 8; ni++) {
                const int r = nbase + 8 * ni + g;
                uint32_t bh[2], bl[2];
                bh[0] = __float_as_uint(xhi[r][kb]);
                bh[1] = __float_as_uint(xhi[r][kb + 4]);
                bl[0] = __float_as_uint(xlo[r][kb]);
                bl[1] = __float_as_uint(xlo[r][kb + 4]);
                #pragma unroll
                for (int mi = 0; mi < 2; mi++) {
                    mma_tf32(c[mi][ni], ah[mi], bh);   // hi*hi
                    mma_tf32(c[mi][ni], ah[mi], bl);   // hi*lo
                    mma_tf32(c[mi][ni], al[mi], bh);   // lo*hi
                }
            }
        }
    }

    // Epilogue: z += b[k]; s = half(__sinf(z)); store to g_sT[k][n]
    #pragma unroll
    for (int mi = 0; mi < 2; mi++) {
        const int rr0 = k0 + ibase + 16 * mi + g;
        const float bv0 = b[rr0];
        const float bv1 = b[rr0 + 8];
        #pragma unroll
        for (int ni = 0; ni < 8; ni++) {
            const int cc = n0 + nbase + 8 * ni + 2 * t4;
            __half2 h0 = __floats2half2_rn(__sinf(c[mi][ni][0] + bv0),
                                           __sinf(c[mi][ni][1] + bv0));
            __half2 h1 = __floats2half2_rn(__sinf(c[mi][ni][2] + bv1),
                                           __sinf(c[mi][ni][3] + bv1));
            *(uint32_t*)&g_sT[(size_t)rr0 * N_OBS + cc]       = *(uint32_t*)&h0;
            *(uint32_t*)&g_sT[(size_t)(rr0 + 8) * N_OBS + cc] = *(uint32_t*)&h1;
        }
    }
}

// ---------------------------------------------------------------------------
// Kernel B: partial Gram via fp16 mma.m16n8k16 + ldmatrix, cp.async dbl-buffer.
// grid = (36 pairs, 8 splits), 256 threads (8 warps 4x2, warp tile 32x64).
// ---------------------------------------------------------------------------
#define B_ROWB  80                    // 64B data + 16B pad
#define B_OPB   (128 * B_ROWB)        // 10240 B per operand tile
#define B_BUF   (2 * B_OPB)
#define B_SMEMB (2 * B_BUF)           // 40960 B double-buffered
#define B_NCH   8                     // 256 n per CTA / 32 per chunk

__global__ void __launch_bounds__(256, 3) kernelB_f16() {
    __shared__ __align__(16) char sm[B_SMEMB];

    const int tid = threadIdx.x;
    const int wid = tid >> 5;
    const int lid = tid & 31;
    const int g   = lid >> 2;
    const int t4  = lid & 3;

    int tr, tc; pair_from_idx(blockIdx.x, tr, tc);
    const int i0 = tr * 128, l0 = tc * 128;
    const bool diag = (tr == tc);
    const int ops  = diag ? 1 : 2;
    const int nb   = blockIdx.y * (N_OBS / NSPLIT);

    const uint32_t sb = smem_u32(sm);
    const int wr = wid & 3;
    const int wc = wid >> 2;
    const int ibase = wr * 32, lbase = wc * 64;

    float c[2][8][4];
    #pragma unroll
    for (int mi = 0; mi < 2; mi++)
        #pragma unroll
        for (int ni = 0; ni < 8; ni++)
            #pragma unroll
            for (int t = 0; t < 4; t++) c[mi][ni][t] = 0.f;

    auto stage = [&](int ch, int buf) {
        const int n0 = nb + ch * 32;
        const int tot = ops << 9;
        for (int e = tid; e < tot; e += 256) {
            const int op  = e >> 9;
            const int idx = e & 511;
            const int row = idx >> 2;
            const int c16 = idx & 3;
            const int grow = (op ? l0 : i0) + row;
            cp_async16(sb + (uint32_t)(buf * B_BUF + op * B_OPB + row * B_ROWB + c16 * 16),
                       &g_sT[(size_t)grow * N_OBS + n0 + c16 * 8]);
        }
    };

    const uint32_t aOff0 = (uint32_t)((ibase + (lid & 15)) * B_ROWB + (lid >> 4) * 16);
    const uint32_t bRow  = (uint32_t)(lbase + ((lid >> 4) << 3) + (lid & 7));
    const uint32_t bOff0 = bRow * B_ROWB + ((lid >> 3) & 1) * 16;

    stage(0, 0);
    CP_COMMIT();

    for (int ch = 0; ch < B_NCH; ch++) {
        const int buf = ch & 1;
        if (ch + 1 < B_NCH) { stage(ch + 1, buf ^ 1); CP_COMMIT(); CP_WAIT1(); }
        else                { CP_WAIT0(); }
        __syncthreads();

        const uint32_t aBase = sb + buf * B_BUF;
        const uint32_t bBase = diag ? aBase : aBase + B_OPB;

        #pragma unroll
        for (int ks = 0; ks < 2; ks++) {
            uint32_t a[2][4];
            #pragma unroll
            for (int mi = 0; mi < 2; mi++)
                ldmatrix_x4(a[mi], aBase + aOff0 + (uint32_t)(mi * 16 * B_ROWB + ks * 32));
            #pragma unroll
            for (int p = 0; p < 4; p++) {
                uint32_t bb[4];
                ldmatrix_x4(bb, bBase + bOff0 + (uint32_t)(p * 16 * B_ROWB + ks * 32));
                #pragma unroll
                for (int mi = 0; mi < 2; mi++) {
                    mma_f16(c[mi][2 * p],     a[mi], &bb[0]);
                    mma_f16(c[mi][2 * p + 1], a[mi], &bb[2]);
                }
            }
        }
        __syncthreads();
    }

    const float sc = (2.0f / (float)KH) / (float)N_OBS;
    float* dst = &g_Mp[((size_t)blockIdx.y * NPAIR + blockIdx.x) * (128 * 128)];
    #pragma unroll
    for (int mi = 0; mi < 2; mi++) {
        const int rr = ibase + 16 * mi + g;
        #pragma unroll
        for (int ni = 0; ni < 8; ni++) {
            const int cc = lbase + 8 * ni + 2 * t4;
            float2 v0 = make_float2(c[mi][ni][0] * sc, c[mi][ni][1] * sc);
            float2 v1 = make_float2(c[mi][ni][2] * sc, c[mi][ni][3] * sc);
            *(float2*)&dst[(size_t)rr * 128 + cc]       = v0;
            *(float2*)&dst[(size_t)(rr + 8) * 128 + cc] = v1;
        }
    }
}

// ---------------------------------------------------------------------------
// Kernel C (fused R): Ms tile reduced from the 8 split-partials in-prologue,
// then A[d,k,l] = Ms[k,l] * w[k,d] * w[l,d]. 256 MB store-bound.
// grid = (KH/128 l-tiles, KH/8 k-blocks), 256 threads, 8 CTAs/SM.
// ---------------------------------------------------------------------------
#define C_KT 8
#define C_LT 128
#define C_WPAD 132

__global__ void __launch_bounds__(256, 8) kernelC(const float* __restrict__ w,
                                                  float* __restrict__ out) {
    __shared__ __align__(16) float wld[32][C_WPAD];     // 16.9 KB
    __shared__ __align__(16) float Ms[C_KT][C_LT];      // 4 KB
    __shared__ float wks[DIN][C_KT + 1];                // 2.3 KB

    const int tid = threadIdx.x;
    const int lt  = blockIdx.x;
    const int l0  = lt * C_LT;
    const int k0  = blockIdx.y * C_KT;
    const int kt  = k0 >> 7;
    const int ko  = k0 & 127;                           // row offset inside k-tile

    // ---- fused reduction: Ms[kk][li] = sum_s Mp[s][pair] (transposed if kt>lt)
    if (kt <= lt) {
        const size_t pbase = (size_t)idx_from_pair(kt, lt) * (128 * 128);
        const int kk  = tid >> 5;                       // 0..7
        const int li4 = (tid & 31) * 4;
        float4 v = make_float4(0.f, 0.f, 0.f, 0.f);
        #pragma unroll
        for (int s = 0; s < NSPLIT; s++) {
            const float4 p = *(const float4*)
                &g_Mp[(size_t)s * NPAIR * (128 * 128) + pbase + (size_t)(ko + kk) * 128 + li4];
            v.x += p.x; v.y += p.y; v.z += p.z; v.w += p.w;
        }
        *(float4*)&Ms[kk][li4] = v;
    } else {
        const size_t pbase = (size_t)idx_from_pair(lt, kt) * (128 * 128);
        const int li = tid >> 1;                        // 0..127
        const int h  = tid & 1;
        float4 v = make_float4(0.f, 0.f, 0.f, 0.f);
        #pragma unroll
        for (int s = 0; s < NSPLIT; s++) {
            const float4 p = *(const float4*)
                &g_Mp[(size_t)s * NPAIR * (128 * 128) + pbase + (size_t)li * 128 + ko + h * 4];
            v.x += p.x; v.y += p.y; v.z += p.z; v.w += p.w;
        }
        Ms[h * 4 + 0][li] = v.x;
        Ms[h * 4 + 1][li] = v.y;
        Ms[h * 4 + 2][li] = v.z;
        Ms[h * 4 + 3][li] = v.w;
    }

    for (int i = tid; i < C_KT * DIN; i += 256) {
        const int kk = i >> 6, d = i & 63;
        wks[d][kk] = w[(size_t)(k0 + kk) * DIN + d];
    }

    const int j     = tid >> 5;
    const int lane4 = (tid & 31) * 4;

    float4 M4;
    const size_t base = (size_t)(k0 + j) * KH + l0 + lane4;

    #pragma unroll
    for (int h = 0; h < 2; h++) {
        __syncthreads();
        for (int i = tid; i < 32 * C_LT; i += 256) {
            const int li = i >> 5, d = i & 31;
            wld[d][li] = w[(size_t)(l0 + li) * DIN + h * 32 + d];
        }
        __syncthreads();
        if (h == 0) M4 = *(const float4*)&Ms[j][lane4];

        #pragma unroll 8
        for (int dd = 0; dd < 32; dd++) {
            const int d = h * 32 + dd;
            const float wk  = wks[d][j];
            const float4 wl = *(const float4*)&wld[dd][lane4];
            float4 o;
            o.x = (M4.x * wk) * wl.x;
            o.y = (M4.y * wk) * wl.y;
            o.z = (M4.z * wk) * wl.z;
            o.w = (M4.w * wk) * wl.w;
            __stcs((float4*)&out[(size_t)d * (size_t)(KH * KH) + base], o);
        }
    }
}

// ---------------------------------------------------------------------------
extern "C" void kernel_launch(void* const* d_in, const int* in_sizes, int n_in,
                              void* d_out, int out_size) {
    (void)in_sizes; (void)n_in; (void)out_size;
    const float* x = (const float*)d_in[0];
    const float* w = (const float*)d_in[1];
    const float* b = (const float*)d_in[2];
    float* out = (float*)d_out;

    kernelA_tc<<<dim3(KH / 128, N_OBS / 128), 256>>>(x, w, b);
    kernelB_f16<<<dim3(NPAIR, NSPLIT), 256>>>();
    kernelC<<<dim3(KH / C_LT, KH / C_KT), 256>>>(w, out);
}

// round 12
// speedup vs baseline: 1.9740x; 1.0425x over previous
#include <cuda_runtime.h>
#include <cuda_fp16.h>
#include <cstdint>

#define N_OBS 2048
#define KH    1024
#define DIN   64
#define NTILE 8          // KH / 128
#define NPAIR 36         // upper-triangle tile pairs
#define NSPLIT 8         // split-K factor for kernelB

// Scratch (device globals: allocation-free per harness rules)
__device__ __half g_sT[KH * N_OBS];                  // 4 MB: sin activations fp16, (k, n)
__device__ float  g_Mp[NSPLIT * NPAIR * 128 * 128];  // 18.9 MB: per-(split,tile) partials (L2-resident)

// ---------------------------------------------------------------------------
// Helpers (compute_103-portable)
// ---------------------------------------------------------------------------
__device__ __forceinline__ void pair_from_idx(int idx, int& tr, int& tc) {
    int t = 0, rem = idx;
    while (rem >= NTILE - t) { rem -= NTILE - t; t++; }
    tr = t; tc = t + rem;
}
__device__ __forceinline__ int idx_from_pair(int tr, int tc) {   // tr <= tc
    return tr * NTILE - (tr * (tr - 1)) / 2 + (tc - tr);
}
__device__ __forceinline__ uint32_t smem_u32(const void* p) {
    uint32_t a;
    asm("{ .reg .u64 t; cvta.to.shared.u64 t, %1; cvt.u32.u64 %0, t; }" : "=r"(a) : "l"(p));
    return a;
}
__device__ __forceinline__ void cp_async16(uint32_t dst, const void* src) {
    asm volatile("cp.async.cg.shared.global [%0], [%1], 16;" :: "r"(dst), "l"(src));
}
#define CP_COMMIT() asm volatile("cp.async.commit_group;" ::: "memory")
#define CP_WAIT1()  asm volatile("cp.async.wait_group 1;" ::: "memory")
#define CP_WAIT0()  asm volatile("cp.async.wait_group 0;" ::: "memory")

__device__ __forceinline__ void ldmatrix_x4(uint32_t* r, uint32_t addr) {
    asm volatile("ldmatrix.sync.aligned.m8n8.x4.shared.b16 {%0,%1,%2,%3}, [%4];"
                 : "=r"(r[0]), "=r"(r[1]), "=r"(r[2]), "=r"(r[3]) : "r"(addr));
}
__device__ __forceinline__ void mma_f16(float* c, const uint32_t* a, const uint32_t* b) {
    asm volatile(
        "mma.sync.aligned.m16n8k16.row.col.f32.f16.f16.f32 "
        "{%0,%1,%2,%3}, {%4,%5,%6,%7}, {%8,%9}, {%0,%1,%2,%3};"
        : "+f"(c[0]), "+f"(c[1]), "+f"(c[2]), "+f"(c[3])
        : "r"(a[0]), "r"(a[1]), "r"(a[2]), "r"(a[3]), "r"(b[0]), "r"(b[1]));
}

// ---------------------------------------------------------------------------
// Kernel A (split-fp16 tensor-core): g_sT[k][n] = half(__sinf(x@w.T + b))
// v = hi + lo (both fp16); z = wh*xh + wh*xl + wl*xh accumulated in fp32
// (fp16 products are exact in fp32; dropped lo*lo term ~2^-22 relative).
// grid = (KH/128, N_OBS/64) = (8,32) = 256 CTAs, 256 thr, warp grid 4(k)x2(n),
// warp tile 32k x 32n. Whole d=64 staged once; ldmatrix fragment loads.
// ---------------------------------------------------------------------------
#define AF_ROWB 144                  // 64 halves (128 B) + 16 B pad: conflict-free
#define AF_WHI  0
#define AF_WLO  (128 * AF_ROWB)
#define AF_XHI  (2 * 128 * AF_ROWB)
#define AF_XLO  (2 * 128 * AF_ROWB + 64 * AF_ROWB)
#define AF_SMEM (2 * 128 * AF_ROWB + 2 * 64 * AF_ROWB)   // 55296 B

__global__ void __launch_bounds__(256) kernelA_f16(const float* __restrict__ x,
                                                   const float* __restrict__ w,
                                                   const float* __restrict__ b) {
    extern __shared__ __align__(16) char smA[];
    const uint32_t sb = smem_u32(smA);

    const int tid = threadIdx.x;
    const int wid = tid >> 5;
    const int lid = tid & 31;
    const int g   = lid >> 2;
    const int t4  = lid & 3;

    const int k0 = blockIdx.x * 128;
    const int n0 = blockIdx.y * 64;

    const int wr = wid & 3;              // k offset wr*32
    const int wc = wid >> 2;             // n offset wc*32
    const int ibase = wr * 32, nbase = wc * 32;

    // ---- stage w (128 rows) and x (64 rows) as (hi, lo) half pairs
    for (int e = tid; e < 128 * 16; e += 256) {          // w: 2048 float4
        const int row = e >> 4, c4 = (e & 15) * 4;
        const float4 v = *(const float4*)&w[(size_t)(k0 + row) * DIN + c4];
        __half h0 = __float2half_rn(v.x), h1 = __float2half_rn(v.y);
        __half h2 = __float2half_rn(v.z), h3 = __float2half_rn(v.w);
        __half l0 = __float2half_rn(v.x - __half2float(h0));
        __half l1 = __float2half_rn(v.y - __half2float(h1));
        __half l2 = __float2half_rn(v.z - __half2float(h2));
        __half l3 = __float2half_rn(v.w - __half2float(h3));
        __half2 hA = __halves2half2(h0, h1), hB = __halves2half2(h2, h3);
        __half2 lA = __halves2half2(l0, l1), lB = __halves2half2(l2, l3);
        uint2 uh; uh.x = *(uint32_t*)&hA; uh.y = *(uint32_t*)&hB;
        uint2 ul; ul.x = *(uint32_t*)&lA; ul.y = *(uint32_t*)&lB;
        *(uint2*)(smA + AF_WHI + row * AF_ROWB + c4 * 2) = uh;
        *(uint2*)(smA + AF_WLO + row * AF_ROWB + c4 * 2) = ul;
    }
    for (int e = tid; e < 64 * 16; e += 256) {           // x: 1024 float4
        const int row = e >> 4, c4 = (e & 15) * 4;
        const float4 v = *(const float4*)&x[(size_t)(n0 + row) * DIN + c4];
        __half h0 = __float2half_rn(v.x), h1 = __float2half_rn(v.y);
        __half h2 = __float2half_rn(v.z), h3 = __float2half_rn(v.w);
        __half l0 = __float2half_rn(v.x - __half2float(h0));
        __half l1 = __float2half_rn(v.y - __half2float(h1));
        __half l2 = __float2half_rn(v.z - __half2float(h2));
        __half l3 = __float2half_rn(v.w - __half2float(h3));
        __half2 hA = __halves2half2(h0, h1), hB = __halves2half2(h2, h3);
        __half2 lA = __halves2half2(l0, l1), lB = __halves2half2(l2, l3);
        uint2 uh; uh.x = *(uint32_t*)&hA; uh.y = *(uint32_t*)&hB;
        uint2 ul; ul.x = *(uint32_t*)&lA; ul.y = *(uint32_t*)&lB;
        *(uint2*)(smA + AF_XHI + row * AF_ROWB + c4 * 2) = uh;
        *(uint2*)(smA + AF_XLO + row * AF_ROWB + c4 * 2) = ul;
    }
    __syncthreads();

    float c[2][4][4];
    #pragma unroll
    for (int mi = 0; mi < 2; mi++)
        #pragma unroll
        for (int ni = 0; ni < 4; ni++)
            #pragma unroll
            for (int t = 0; t < 4; t++) c[mi][ni][t] = 0.f;

    // ldmatrix addressing (same scheme as kernelB, row stride 144 B)
    const uint32_t aOff0 = (uint32_t)((ibase + (lid & 15)) * AF_ROWB + (lid >> 4) * 16);
    const uint32_t bRow  = (uint32_t)(nbase + ((lid >> 4) << 3) + (lid & 7));
    const uint32_t bOff0 = bRow * AF_ROWB + ((lid >> 3) & 1) * 16;

    #pragma unroll
    for (int ks = 0; ks < 4; ks++) {                     // 4 x k16 over d=64
        uint32_t ah[2][4], al[2][4];
        #pragma unroll
        for (int mi = 0; mi < 2; mi++) {
            const uint32_t o = aOff0 + (uint32_t)(mi * 16 * AF_ROWB + ks * 32);
            ldmatrix_x4(ah[mi], sb + AF_WHI + o);
            ldmatrix_x4(al[mi], sb + AF_WLO + o);
        }
        #pragma unroll
        for (int p = 0; p < 2; p++) {                    // two groups of 16 n-rows
            const uint32_t o = bOff0 + (uint32_t)(p * 16 * AF_ROWB + ks * 32);
            uint32_t bh[4], bl[4];
            ldmatrix_x4(bh, sb + AF_XHI + o);
            ldmatrix_x4(bl, sb + AF_XLO + o);
            #pragma unroll
            for (int mi = 0; mi < 2; mi++) {
                mma_f16(c[mi][2 * p],     ah[mi], &bh[0]);   // hi*hi
                mma_f16(c[mi][2 * p],     ah[mi], &bl[0]);   // hi*lo
                mma_f16(c[mi][2 * p],     al[mi], &bh[0]);   // lo*hi
                mma_f16(c[mi][2 * p + 1], ah[mi], &bh[2]);
                mma_f16(c[mi][2 * p + 1], ah[mi], &bl[2]);
                mma_f16(c[mi][2 * p + 1], al[mi], &bh[2]);
            }
        }
    }

    // Epilogue: z += b[k]; s = half(__sinf(z)); store g_sT[k][n]
    #pragma unroll
    for (int mi = 0; mi < 2; mi++) {
        const int rr0 = k0 + ibase + 16 * mi + g;
        const float bv0 = b[rr0];
        const float bv1 = b[rr0 + 8];
        #pragma unroll
        for (int ni = 0; ni < 4; ni++) {
            const int cc = n0 + nbase + 8 * ni + 2 * t4;
            __half2 h0 = __floats2half2_rn(__sinf(c[mi][ni][0] + bv0),
                                           __sinf(c[mi][ni][1] + bv0));
            __half2 h1 = __floats2half2_rn(__sinf(c[mi][ni][2] + bv1),
                                           __sinf(c[mi][ni][3] + bv1));
            *(uint32_t*)&g_sT[(size_t)rr0 * N_OBS + cc]       = *(uint32_t*)&h0;
            *(uint32_t*)&g_sT[(size_t)(rr0 + 8) * N_OBS + cc] = *(uint32_t*)&h1;
        }
    }
}

// ---------------------------------------------------------------------------
// Kernel B: partial Gram via fp16 mma.m16n8k16 + ldmatrix, cp.async dbl-buffer.
// grid = (36 pairs, 8 splits), 256 threads (8 warps 4x2, warp tile 32x64).
// ---------------------------------------------------------------------------
#define B_ROWB  80                    // 64B data + 16B pad
#define B_OPB   (128 * B_ROWB)
#define B_BUF   (2 * B_OPB)
#define B_SMEMB (2 * B_BUF)           // 40960 B double-buffered
#define B_NCH   8                     // 256 n per CTA / 32 per chunk

__global__ void __launch_bounds__(256, 3) kernelB_f16() {
    __shared__ __align__(16) char sm[B_SMEMB];

    const int tid = threadIdx.x;
    const int wid = tid >> 5;
    const int lid = tid & 31;
    const int g   = lid >> 2;
    const int t4  = lid & 3;

    int tr, tc; pair_from_idx(blockIdx.x, tr, tc);
    const int i0 = tr * 128, l0 = tc * 128;
    const bool diag = (tr == tc);
    const int ops  = diag ? 1 : 2;
    const int nb   = blockIdx.y * (N_OBS / NSPLIT);

    const uint32_t sb = smem_u32(sm);
    const int wr = wid & 3;
    const int wc = wid >> 2;
    const int ibase = wr * 32, lbase = wc * 64;

    float c[2][8][4];
    #pragma unroll
    for (int mi = 0; mi < 2; mi++)
        #pragma unroll
        for (int ni = 0; ni < 8; ni++)
            #pragma unroll
            for (int t = 0; t < 4; t++) c[mi][ni][t] = 0.f;

    auto stage = [&](int ch, int buf) {
        const int n0 = nb + ch * 32;
        const int tot = ops << 9;
        for (int e = tid; e < tot; e += 256) {
            const int op  = e >> 9;
            const int idx = e & 511;
            const int row = idx >> 2;
            const int c16 = idx & 3;
            const int grow = (op ? l0 : i0) + row;
            cp_async16(sb + (uint32_t)(buf * B_BUF + op * B_OPB + row * B_ROWB + c16 * 16),
                       &g_sT[(size_t)grow * N_OBS + n0 + c16 * 8]);
        }
    };

    const uint32_t aOff0 = (uint32_t)((ibase + (lid & 15)) * B_ROWB + (lid >> 4) * 16);
    const uint32_t bRow  = (uint32_t)(lbase + ((lid >> 4) << 3) + (lid & 7));
    const uint32_t bOff0 = bRow * B_ROWB + ((lid >> 3) & 1) * 16;

    stage(0, 0);
    CP_COMMIT();

    for (int ch = 0; ch < B_NCH; ch++) {
        const int buf = ch & 1;
        if (ch + 1 < B_NCH) { stage(ch + 1, buf ^ 1); CP_COMMIT(); CP_WAIT1(); }
        else                { CP_WAIT0(); }
        __syncthreads();

        const uint32_t aBase = sb + buf * B_BUF;
        const uint32_t bBase = diag ? aBase : aBase + B_OPB;

        #pragma unroll
        for (int ks = 0; ks < 2; ks++) {
            uint32_t a[2][4];
            #pragma unroll
            for (int mi = 0; mi < 2; mi++)
                ldmatrix_x4(a[mi], aBase + aOff0 + (uint32_t)(mi * 16 * B_ROWB + ks * 32));
            #pragma unroll
            for (int p = 0; p < 4; p++) {
                uint32_t bb[4];
                ldmatrix_x4(bb, bBase + bOff0 + (uint32_t)(p * 16 * B_ROWB + ks * 32));
                #pragma unroll
                for (int mi = 0; mi < 2; mi++) {
                    mma_f16(c[mi][2 * p],     a[mi], &bb[0]);
                    mma_f16(c[mi][2 * p + 1], a[mi], &bb[2]);
                }
            }
        }
        __syncthreads();
    }

    const float sc = (2.0f / (float)KH) / (float)N_OBS;
    float* dst = &g_Mp[((size_t)blockIdx.y * NPAIR + blockIdx.x) * (128 * 128)];
    #pragma unroll
    for (int mi = 0; mi < 2; mi++) {
        const int rr = ibase + 16 * mi + g;
        #pragma unroll
        for (int ni = 0; ni < 8; ni++) {
            const int cc = lbase + 8 * ni + 2 * t4;
            float2 v0 = make_float2(c[mi][ni][0] * sc, c[mi][ni][1] * sc);
            float2 v1 = make_float2(c[mi][ni][2] * sc, c[mi][ni][3] * sc);
            *(float2*)&dst[(size_t)rr * 128 + cc]       = v0;
            *(float2*)&dst[(size_t)(rr + 8) * 128 + cc] = v1;
        }
    }
}

// ---------------------------------------------------------------------------
// Kernel C (fused R): Ms tile reduced from the 8 split-partials in-prologue,
// then A[d,k,l] = Ms[k,l] * w[k,d] * w[l,d]. 256 MB store-bound.
// grid = (KH/128 l-tiles, KH/8 k-blocks), 256 threads, 8 CTAs/SM.
// ---------------------------------------------------------------------------
#define C_KT 8
#define C_LT 128
#define C_WPAD 132

__global__ void __launch_bounds__(256, 8) kernelC(const float* __restrict__ w,
                                                  float* __restrict__ out) {
    __shared__ __align__(16) float wld[32][C_WPAD];     // 16.9 KB
    __shared__ __align__(16) float Ms[C_KT][C_LT];      // 4 KB
    __shared__ float wks[DIN][C_KT + 1];                // 2.3 KB

    const int tid = threadIdx.x;
    const int lt  = blockIdx.x;
    const int l0  = lt * C_LT;
    const int k0  = blockIdx.y * C_KT;
    const int kt  = k0 >> 7;
    const int ko  = k0 & 127;

    if (kt <= lt) {
        const size_t pbase = (size_t)idx_from_pair(kt, lt) * (128 * 128);
        const int kk  = tid >> 5;
        const int li4 = (tid & 31) * 4;
        float4 v = make_float4(0.f, 0.f, 0.f, 0.f);
        #pragma unroll
        for (int s = 0; s < NSPLIT; s++) {
            const float4 p = *(const float4*)
                &g_Mp[(size_t)s * NPAIR * (128 * 128) + pbase + (size_t)(ko + kk) * 128 + li4];
            v.x += p.x; v.y += p.y; v.z += p.z; v.w += p.w;
        }
        *(float4*)&Ms[kk][li4] = v;
    } else {
        const size_t pbase = (size_t)idx_from_pair(lt, kt) * (128 * 128);
        const int li = tid >> 1;
        const int h  = tid & 1;
        float4 v = make_float4(0.f, 0.f, 0.f, 0.f);
        #pragma unroll
        for (int s = 0; s < NSPLIT; s++) {
            const float4 p = *(const float4*)
                &g_Mp[(size_t)s * NPAIR * (128 * 128) + pbase + (size_t)li * 128 + ko + h * 4];
            v.x += p.x; v.y += p.y; v.z += p.z; v.w += p.w;
        }
        Ms[h * 4 + 0][li] = v.x;
        Ms[h * 4 + 1][li] = v.y;
        Ms[h * 4 + 2][li] = v.z;
        Ms[h * 4 + 3][li] = v.w;
    }

    for (int i = tid; i < C_KT * DIN; i += 256) {
        const int kk = i >> 6, d = i & 63;
        wks[d][kk] = w[(size_t)(k0 + kk) * DIN + d];
    }

    const int j     = tid >> 5;
    const int lane4 = (tid & 31) * 4;

    float4 M4;
    const size_t base = (size_t)(k0 + j) * KH + l0 + lane4;

    #pragma unroll
    for (int h = 0; h < 2; h++) {
        __syncthreads();
        for (int i = tid; i < 32 * C_LT; i += 256) {
            const int li = i >> 5, d = i & 31;
            wld[d][li] = w[(size_t)(l0 + li) * DIN + h * 32 + d];
        }
        __syncthreads();
        if (h == 0) M4 = *(const float4*)&Ms[j][lane4];

        #pragma unroll 8
        for (int dd = 0; dd < 32; dd++) {
            const int d = h * 32 + dd;
            const float wk  = wks[d][j];
            const float4 wl = *(const float4*)&wld[dd][lane4];
            float4 o;
            o.x = (M4.x * wk) * wl.x;
            o.y = (M4.y * wk) * wl.y;
            o.z = (M4.z * wk) * wl.z;
            o.w = (M4.w * wk) * wl.w;
            __stcs((float4*)&out[(size_t)d * (size_t)(KH * KH) + base], o);
        }
    }
}

// ---------------------------------------------------------------------------
extern "C" void kernel_launch(void* const* d_in, const int* in_sizes, int n_in,
                              void* d_out, int out_size) {
    (void)in_sizes; (void)n_in; (void)out_size;
    const float* x = (const float*)d_in[0];
    const float* w = (const float*)d_in[1];
    const float* b = (const float*)d_in[2];
    float* out = (float*)d_out;

    cudaFuncSetAttribute(kernelA_f16, cudaFuncAttributeMaxDynamicSharedMemorySize, AF_SMEM);

    kernelA_f16<<<dim3(KH / 128, N_OBS / 64), 256, AF_SMEM>>>(x, w, b);
    kernelB_f16<<<dim3(NPAIR, NSPLIT), 256>>>();
    kernelC<<<dim3(KH / C_LT, KH / C_KT), 256>>>(w, out);
}